// round 14
// baseline (speedup 1.0000x reference)
#include <cuda_runtime.h>
#include <math.h>
#include <stdint.h>

#define DEPTH 24
#define DM    192
#define DI    384
#define DS    16
#define DR    12
#define BATCH 4
#define LSEQ  401
#define NCLS  22
#define XD    44
#define EPSV  1e-5f
#define NC    31
#define CL    13
#define ROWS  (BATCH*LSEQ)     // 1604
#define ROWS2 (2*BATCH*LSEQ)   // 3208

// ---------------- scratch ----------------------------------------------------
__device__ float g_res [ROWS*DM];
__device__ float g_hid [ROWS*DM];
__device__ float g_hid2[ROWS*DM];
__device__ float g_hn  [ROWS*DM];
__device__ float g_xz  [ROWS*2*DI];
__device__ float g_xx  [ROWS2*DI];
__device__ float g_dt  [ROWS2*DI];
__device__ float g_dbl [ROWS2*XD];
__device__ float g_dbl2[ROWS2*XD];
__device__ float g_y   [ROWS2*DI];
__device__ float g_Aexp[2*DEPTH*DI*DS];
__device__ int   g_Aflag[2*DEPTH*DI];
__device__ float g_hloc[2*BATCH*NC*DS*DI];
__device__ float g_S   [2*BATCH*NC*DI];

__device__ __forceinline__ float siluf(float x) { return x / (1.f + __expf(-x)); }
__device__ __forceinline__ float softplusf(float x) {
    return x > 20.f ? x : log1pf(__expf(x));
}
__device__ __forceinline__ float4 add4(float4 a, float4 b) {
    return make_float4(a.x + b.x, a.y + b.y, a.z + b.z, a.w + b.w);
}
__device__ __forceinline__ uint32_t f2tf(float f) {
    uint32_t r;
    asm("cvt.rna.tf32.f32 %0, %1;" : "=r"(r) : "f"(f));
    return r;
}
// split v into tf32 hi + tf32 lo (3xTF32 compensation)
__device__ __forceinline__ void tfsplit(float v, uint32_t& hi, uint32_t& lo) {
    hi = f2tf(v);
    lo = f2tf(v - __uint_as_float(hi));
}
__device__ __forceinline__ void mma8(float* c, uint32_t a0, uint32_t a1,
                                     uint32_t a2, uint32_t a3,
                                     uint32_t b0, uint32_t b1) {
    asm volatile(
        "mma.sync.aligned.m16n8k8.row.col.f32.tf32.tf32.f32 "
        "{%0,%1,%2,%3},{%4,%5,%6,%7},{%8,%9},{%0,%1,%2,%3};"
        : "+f"(c[0]), "+f"(c[1]), "+f"(c[2]), "+f"(c[3])
        : "r"(a0), "r"(a1), "r"(a2), "r"(a3), "r"(b0), "r"(b1));
}

// ---------------- prep: A = -exp(A_log); detect geometric structure ----------
__global__ void k_prepA(const float* __restrict__ Alog, const float* __restrict__ Ablog) {
    int i = blockIdx.x * blockDim.x + threadIdx.x;
    if (i >= 2 * DEPTH * DI) return;
    int dir = i / (DEPTH * DI);
    int rest = i - dir * (DEPTH * DI);
    const float* src = (dir ? Ablog : Alog) + (size_t)rest * DS;
    float A[DS];
#pragma unroll
    for (int n = 0; n < DS; n++) A[n] = -__expf(src[n]);
    float A0 = A[0];
    bool ok = true;
#pragma unroll
    for (int n = 1; n < DS; n++) {
        float tgt = (float)(n + 1) * A0;
        ok = ok && (fabsf(A[n] - tgt) <= 1e-4f * fabsf(tgt) + 1e-30f);
    }
#pragma unroll
    for (int n = 0; n < DS; n++) g_Aexp[(size_t)i * DS + n] = A[n];
    g_Aflag[i] = ok ? 1 : 0;
}

// ---------------- patch embed + cls + pos ------------------------------------
__global__ void k_embed(const float* __restrict__ x, const float* __restrict__ pew,
                        const float* __restrict__ peb, const float* __restrict__ cls,
                        const float* __restrict__ pos) {
    int t = blockIdx.x, b = blockIdx.y, c = threadIdx.x;
    float v;
    __shared__ float patch[256];
    if (t == 0) {
        v = cls[c] + pos[c];
    } else {
        int p = t - 1;
        int ph = p / 200, pw = p % 200;
        for (int i = c; i < 256; i += DM)
            patch[i] = x[(size_t)b * 32 * 3200 + (size_t)(ph * 16 + i / 16) * 3200
                         + pw * 16 + (i % 16)];
        __syncthreads();
        float acc = peb[c];
        const float* wc = pew + (size_t)c * 256;
#pragma unroll 8
        for (int i = 0; i < 256; i++) acc = fmaf(patch[i], __ldg(wc + i), acc);
        v = acc + pos[(size_t)t * DM + c];
    }
    size_t o = ((size_t)b * LSEQ + t) * DM + c;
    g_res[o] = v;
    g_hid[o] = v;
    g_hid2[o] = 0.f;
}

// ---------------- residual += hid + hid2; rmsnorm ----------------------------
__global__ void k_resnorm(const float* __restrict__ nw) {
    int r = blockIdx.x;
    int c = threadIdx.x;
    __shared__ float red[6];
    size_t o = (size_t)r * DM + c;
    float v = g_res[o] + g_hid[o] + g_hid2[o];
    g_res[o] = v;
    float s = v * v;
#pragma unroll
    for (int ofs = 16; ofs > 0; ofs >>= 1) s += __shfl_xor_sync(0xffffffffu, s, ofs);
    if ((c & 31) == 0) red[c >> 5] = s;
    __syncthreads();
    float tot = red[0] + red[1] + red[2] + red[3] + red[4] + red[5];
    float rs = rsqrtf(tot / (float)DM + EPSV);
    g_hn[o] = v * rs * nw[c];
}

// ======== 3xTF32 tensor-core GEMM: C[M,N] = A[M,K'] @ W[N,K']^T ==============
// 64x64 block tile, 8 warps (each 16x32), m16n8k8 tf32 mma, hi/lo compensation.
// blockIdx.z selects K-slice [z*klen, (z+1)*klen) and output buffer C0/C1.
#define MM_LD 68
__global__ __launch_bounds__(256)
void k_mma(const float* __restrict__ A, const float* __restrict__ W,
           float* __restrict__ C0, float* __restrict__ C1,
           int M, int N, int ldA, int klen, int ldC) {
    __shared__ uint32_t Ah[16 * MM_LD], Al[16 * MM_LD];
    __shared__ uint32_t Wh[16 * MM_LD], Wl[16 * MM_LD];
    int tid = threadIdx.x;
    int row0 = blockIdx.y * 64, col0 = blockIdx.x * 64;
    int kbeg = blockIdx.z * klen;
    float* C = blockIdx.z ? C1 : C0;
    int wid = tid >> 5, lane = tid & 31;
    int wm = wid & 3, wn = wid >> 2;
    int gid = lane >> 2, tig = lane & 3;
    float acc[4][4];
#pragma unroll
    for (int j = 0; j < 4; j++)
#pragma unroll
        for (int i = 0; i < 4; i++) acc[j][i] = 0.f;

    int m = tid >> 2, kq = tid & 3;
    for (int k0 = kbeg; k0 < kbeg + klen; k0 += 16) {
        float4 va = make_float4(0.f, 0.f, 0.f, 0.f);
        if (row0 + m < M)
            va = __ldg((const float4*)(A + (size_t)(row0 + m) * ldA + k0 + kq * 4));
        {
            uint32_t h, lo;
            tfsplit(va.x, h, lo); Ah[(kq*4+0)*MM_LD+m] = h; Al[(kq*4+0)*MM_LD+m] = lo;
            tfsplit(va.y, h, lo); Ah[(kq*4+1)*MM_LD+m] = h; Al[(kq*4+1)*MM_LD+m] = lo;
            tfsplit(va.z, h, lo); Ah[(kq*4+2)*MM_LD+m] = h; Al[(kq*4+2)*MM_LD+m] = lo;
            tfsplit(va.w, h, lo); Ah[(kq*4+3)*MM_LD+m] = h; Al[(kq*4+3)*MM_LD+m] = lo;
        }
        float4 vw = make_float4(0.f, 0.f, 0.f, 0.f);
        if (col0 + m < N)
            vw = __ldg((const float4*)(W + (size_t)(col0 + m) * ldA + k0 + kq * 4));
        {
            uint32_t h, lo;
            tfsplit(vw.x, h, lo); Wh[(kq*4+0)*MM_LD+m] = h; Wl[(kq*4+0)*MM_LD+m] = lo;
            tfsplit(vw.y, h, lo); Wh[(kq*4+1)*MM_LD+m] = h; Wl[(kq*4+1)*MM_LD+m] = lo;
            tfsplit(vw.z, h, lo); Wh[(kq*4+2)*MM_LD+m] = h; Wl[(kq*4+2)*MM_LD+m] = lo;
            tfsplit(vw.w, h, lo); Wh[(kq*4+3)*MM_LD+m] = h; Wl[(kq*4+3)*MM_LD+m] = lo;
        }
        __syncthreads();
#pragma unroll
        for (int kk = 0; kk < 16; kk += 8) {
            int ra = (kk + tig) * MM_LD + wm * 16 + gid;
            int rb = (kk + tig + 4) * MM_LD + wm * 16 + gid;
            uint32_t ah0 = Ah[ra],     ah1 = Ah[ra + 8];
            uint32_t ah2 = Ah[rb],     ah3 = Ah[rb + 8];
            uint32_t al0 = Al[ra],     al1 = Al[ra + 8];
            uint32_t al2 = Al[rb],     al3 = Al[rb + 8];
#pragma unroll
            for (int j = 0; j < 4; j++) {
                int nb = wn * 32 + j * 8;
                int c0 = (kk + tig) * MM_LD + nb + gid;
                int c1 = (kk + tig + 4) * MM_LD + nb + gid;
                uint32_t bh0 = Wh[c0], bh1 = Wh[c1];
                uint32_t bl0 = Wl[c0], bl1 = Wl[c1];
                mma8(acc[j], ah0, ah1, ah2, ah3, bl0, bl1);   // hi*lo
                mma8(acc[j], al0, al1, al2, al3, bh0, bh1);   // lo*hi
                mma8(acc[j], ah0, ah1, ah2, ah3, bh0, bh1);   // hi*hi
            }
        }
        __syncthreads();
    }
    int rs0 = row0 + wm * 16 + gid;
#pragma unroll
    for (int j = 0; j < 4; j++) {
        int cc = col0 + wn * 32 + j * 8 + 2 * tig;
        if (rs0 < M) {
            if (cc < N)     C[(size_t)rs0 * ldC + cc]     = acc[j][0];
            if (cc + 1 < N) C[(size_t)rs0 * ldC + cc + 1] = acc[j][1];
        }
        if (rs0 + 8 < M) {
            if (cc < N)     C[(size_t)(rs0 + 8) * ldC + cc]     = acc[j][2];
            if (cc + 1 < N) C[(size_t)(rs0 + 8) * ldC + cc + 1] = acc[j][3];
        }
    }
}

// ======== 3xTF32 out_proj GEMM with gated A = (yf+yb)*silu(z), K-split x2 ====
__global__ __launch_bounds__(256)
void k_mma_out(const float* __restrict__ W) {
    __shared__ uint32_t Ah[16 * MM_LD], Al[16 * MM_LD];
    __shared__ uint32_t Wh[16 * MM_LD], Wl[16 * MM_LD];
    int tid = threadIdx.x;
    int row0 = blockIdx.y * 64, col0 = blockIdx.x * 64;
    int kbeg = blockIdx.z * (DI / 2);
    float* C = blockIdx.z ? g_hid2 : g_hid;
    int wid = tid >> 5, lane = tid & 31;
    int wm = wid & 3, wn = wid >> 2;
    int gid = lane >> 2, tig = lane & 3;
    float acc[4][4];
#pragma unroll
    for (int j = 0; j < 4; j++)
#pragma unroll
        for (int i = 0; i < 4; i++) acc[j][i] = 0.f;

    int m = tid >> 2, kq = tid & 3;
    int r = row0 + m;
    size_t rbk = 0;
    if (r < ROWS) {
        int bb = r / LSEQ, tt = r % LSEQ;
        rbk = ((size_t)(BATCH + bb) * LSEQ + (LSEQ - 1 - tt));
    }
    for (int k0 = kbeg; k0 < kbeg + DI / 2; k0 += 16) {
        float4 a = make_float4(0.f, 0.f, 0.f, 0.f);
        if (r < ROWS) {
            int d0 = k0 + kq * 4;
            float4 yf = __ldg((const float4*)(g_y + (size_t)r * DI + d0));
            float4 yb = __ldg((const float4*)(g_y + rbk * DI + d0));
            float4 z4 = __ldg((const float4*)(g_xz + (size_t)r * 2 * DI + DI + d0));
            a.x = (yf.x + yb.x) * siluf(z4.x);
            a.y = (yf.y + yb.y) * siluf(z4.y);
            a.z = (yf.z + yb.z) * siluf(z4.z);
            a.w = (yf.w + yb.w) * siluf(z4.w);
        }
        {
            uint32_t h, lo;
            tfsplit(a.x, h, lo); Ah[(kq*4+0)*MM_LD+m] = h; Al[(kq*4+0)*MM_LD+m] = lo;
            tfsplit(a.y, h, lo); Ah[(kq*4+1)*MM_LD+m] = h; Al[(kq*4+1)*MM_LD+m] = lo;
            tfsplit(a.z, h, lo); Ah[(kq*4+2)*MM_LD+m] = h; Al[(kq*4+2)*MM_LD+m] = lo;
            tfsplit(a.w, h, lo); Ah[(kq*4+3)*MM_LD+m] = h; Al[(kq*4+3)*MM_LD+m] = lo;
        }
        float4 vw = make_float4(0.f, 0.f, 0.f, 0.f);
        if (col0 + m < DM)
            vw = __ldg((const float4*)(W + (size_t)(col0 + m) * DI + k0 + kq * 4));
        {
            uint32_t h, lo;
            tfsplit(vw.x, h, lo); Wh[(kq*4+0)*MM_LD+m] = h; Wl[(kq*4+0)*MM_LD+m] = lo;
            tfsplit(vw.y, h, lo); Wh[(kq*4+1)*MM_LD+m] = h; Wl[(kq*4+1)*MM_LD+m] = lo;
            tfsplit(vw.z, h, lo); Wh[(kq*4+2)*MM_LD+m] = h; Wl[(kq*4+2)*MM_LD+m] = lo;
            tfsplit(vw.w, h, lo); Wh[(kq*4+3)*MM_LD+m] = h; Wl[(kq*4+3)*MM_LD+m] = lo;
        }
        __syncthreads();
#pragma unroll
        for (int kk = 0; kk < 16; kk += 8) {
            int ra = (kk + tig) * MM_LD + wm * 16 + gid;
            int rb = (kk + tig + 4) * MM_LD + wm * 16 + gid;
            uint32_t ah0 = Ah[ra],     ah1 = Ah[ra + 8];
            uint32_t ah2 = Ah[rb],     ah3 = Ah[rb + 8];
            uint32_t al0 = Al[ra],     al1 = Al[ra + 8];
            uint32_t al2 = Al[rb],     al3 = Al[rb + 8];
#pragma unroll
            for (int j = 0; j < 4; j++) {
                int nb = wn * 32 + j * 8;
                int c0 = (kk + tig) * MM_LD + nb + gid;
                int c1 = (kk + tig + 4) * MM_LD + nb + gid;
                uint32_t bh0 = Wh[c0], bh1 = Wh[c1];
                uint32_t bl0 = Wl[c0], bl1 = Wl[c1];
                mma8(acc[j], ah0, ah1, ah2, ah3, bl0, bl1);
                mma8(acc[j], al0, al1, al2, al3, bh0, bh1);
                mma8(acc[j], ah0, ah1, ah2, ah3, bh0, bh1);
            }
        }
        __syncthreads();
    }
    int rs0 = row0 + wm * 16 + gid;
#pragma unroll
    for (int j = 0; j < 4; j++) {
        int cc = col0 + wn * 32 + j * 8 + 2 * tig;
        if (rs0 < ROWS && cc < DM) {
            C[(size_t)rs0 * DM + cc]     = acc[j][0];
            C[(size_t)rs0 * DM + cc + 1] = acc[j][1];
        }
        if (rs0 + 8 < ROWS && cc < DM) {
            C[(size_t)(rs0 + 8) * DM + cc]     = acc[j][2];
            C[(size_t)(rs0 + 8) * DM + cc + 1] = acc[j][3];
        }
    }
}

// ---------------- causal depthwise conv + silu (both directions) -------------
#define CONV_TT 16
__global__ void k_conv(const float* __restrict__ cw, const float* __restrict__ cb) {
    int dir = blockIdx.z, b = blockIdx.y, tile = blockIdx.x;
    int d = threadIdx.x;
    float w0 = cw[d * 4 + 0], w1 = cw[d * 4 + 1], w2 = cw[d * 4 + 2], w3 = cw[d * 4 + 3];
    float bi = cb[d];
    const float* xzb = g_xz + (size_t)b * LSEQ * 2 * DI + d;
    int t0 = tile * CONV_TT, t1 = min(LSEQ, t0 + CONV_TT);
    for (int t = t0; t < t1; t++) {
        float s = bi;
        if (dir == 0) {
            if (t >= 3) s = fmaf(w0, xzb[(size_t)(t - 3) * 2 * DI], s);
            if (t >= 2) s = fmaf(w1, xzb[(size_t)(t - 2) * 2 * DI], s);
            if (t >= 1) s = fmaf(w2, xzb[(size_t)(t - 1) * 2 * DI], s);
            s = fmaf(w3, xzb[(size_t)t * 2 * DI], s);
        } else {
            int base = LSEQ - 1 - t;
            s = fmaf(w3, xzb[(size_t)base * 2 * DI], s);
            if (t >= 1) s = fmaf(w2, xzb[(size_t)(base + 1) * 2 * DI], s);
            if (t >= 2) s = fmaf(w1, xzb[(size_t)(base + 2) * 2 * DI], s);
            if (t >= 3) s = fmaf(w0, xzb[(size_t)(base + 3) * 2 * DI], s);
        }
        g_xx[(((size_t)dir * BATCH + b) * LSEQ + t) * DI + d] = siluf(s);
    }
}

// ---------------- scan pass A: chunk-local scan (dt_proj fused, stores dt) ---
__global__ __launch_bounds__(DI)
void k_scanA(const float* __restrict__ dtw, const float* __restrict__ dtb,
             const float* __restrict__ Dpl, int l) {
    int dir = blockIdx.z, b = blockIdx.y, c = blockIdx.x;
    int d = threadIdx.x;
    const float* Ap = g_Aexp + (((size_t)dir * DEPTH + l) * DI + d) * DS;
    float A[DS];
#pragma unroll
    for (int n = 0; n < DS; n++) A[n] = Ap[n];
    int flag = g_Aflag[((size_t)dir * DEPTH + l) * DI + d];
    float A0 = A[0];
    float wdt[DR];
#pragma unroll
    for (int j = 0; j < DR; j++) wdt[j] = __ldg(dtw + (size_t)d * DR + j);
    float db0 = dtb[d], Dd = Dpl[d];

    size_t r0 = ((size_t)dir * BATCH + b) * LSEQ;
    int t0 = c * CL, t1 = min(LSEQ, t0 + CL);
    float h[DS];
#pragma unroll
    for (int n = 0; n < DS; n++) h[n] = 0.f;
    float S = 0.f;

    for (int t = t0; t < t1; t++) {
        size_t r = r0 + t;
        const float4* dbq  = (const float4*)(g_dbl  + r * XD);
        const float4* dbq2 = (const float4*)(g_dbl2 + r * XD);
        float4 q0 = add4(__ldg(dbq + 0), __ldg(dbq2 + 0));
        float4 q1 = add4(__ldg(dbq + 1), __ldg(dbq2 + 1));
        float4 q2 = add4(__ldg(dbq + 2), __ldg(dbq2 + 2));
        float4 qB0 = add4(__ldg(dbq + 3), __ldg(dbq2 + 3));
        float4 qB1 = add4(__ldg(dbq + 4), __ldg(dbq2 + 4));
        float4 qB2 = add4(__ldg(dbq + 5), __ldg(dbq2 + 5));
        float4 qB3 = add4(__ldg(dbq + 6), __ldg(dbq2 + 6));
        float4 qC0 = add4(__ldg(dbq + 7), __ldg(dbq2 + 7));
        float4 qC1 = add4(__ldg(dbq + 8), __ldg(dbq2 + 8));
        float4 qC2 = add4(__ldg(dbq + 9), __ldg(dbq2 + 9));
        float4 qC3 = add4(__ldg(dbq + 10), __ldg(dbq2 + 10));
        float d1 = db0, d2 = 0.f;
        d1 = fmaf(q0.x, wdt[0], d1); d2 = fmaf(q0.y, wdt[1], d2);
        d1 = fmaf(q0.z, wdt[2], d1); d2 = fmaf(q0.w, wdt[3], d2);
        d1 = fmaf(q1.x, wdt[4], d1); d2 = fmaf(q1.y, wdt[5], d2);
        d1 = fmaf(q1.z, wdt[6], d1); d2 = fmaf(q1.w, wdt[7], d2);
        d1 = fmaf(q2.x, wdt[8], d1); d2 = fmaf(q2.y, wdt[9], d2);
        d1 = fmaf(q2.z, wdt[10], d1); d2 = fmaf(q2.w, wdt[11], d2);
        float dt = softplusf(d1 + d2);
        g_dt[r * DI + d] = dt;
        float xv = g_xx[r * DI + d];
        float dtx = dt * xv;
        S += dt;
        float Bv[DS] = {qB0.x, qB0.y, qB0.z, qB0.w, qB1.x, qB1.y, qB1.z, qB1.w,
                        qB2.x, qB2.y, qB2.z, qB2.w, qB3.x, qB3.y, qB3.z, qB3.w};
        float Cv[DS] = {qC0.x, qC0.y, qC0.z, qC0.w, qC1.x, qC1.y, qC1.z, qC1.w,
                        qC2.x, qC2.y, qC2.z, qC2.w, qC3.x, qC3.y, qC3.z, qC3.w};
        float acc = 0.f;
        if (flag) {
            float e = __expf(dt * A0);
            float p = e;
#pragma unroll
            for (int n = 0; n < DS; n++) {
                h[n] = fmaf(p, h[n], dtx * Bv[n]);
                acc = fmaf(h[n], Cv[n], acc);
                p *= e;
            }
        } else {
#pragma unroll
            for (int n = 0; n < DS; n++) {
                float a = __expf(dt * A[n]);
                h[n] = fmaf(a, h[n], dtx * Bv[n]);
                acc = fmaf(h[n], Cv[n], acc);
            }
        }
        g_y[r * DI + d] = acc + xv * Dd;
    }
    size_t cb_ = ((size_t)dir * BATCH + b) * NC + c;
#pragma unroll
    for (int n = 0; n < DS; n++) g_hloc[(cb_ * DS + n) * DI + d] = h[n];
    g_S[cb_ * DI + d] = S;
}

// ---------------- scan pass C: carry reconstruction + fixup (loads dt) -------
__global__ __launch_bounds__(DI)
void k_scanC(int l) {
    int dir = blockIdx.z, b = blockIdx.y, c = blockIdx.x + 1;
    int d = threadIdx.x;
    const float* Ap = g_Aexp + (((size_t)dir * DEPTH + l) * DI + d) * DS;
    float A[DS];
#pragma unroll
    for (int n = 0; n < DS; n++) A[n] = Ap[n];
    int flag = g_Aflag[((size_t)dir * DEPTH + l) * DI + d];
    float A0 = A[0];

    size_t cb0 = ((size_t)dir * BATCH + b) * NC;
    float g[DS];
#pragma unroll
    for (int n = 0; n < DS; n++) g[n] = 0.f;
    for (int cc = 0; cc < c; cc++) {
        float Sc = g_S[(cb0 + cc) * DI + d];
        if (flag) {
            float e = __expf(A0 * Sc);
            float p = e;
#pragma unroll
            for (int n = 0; n < DS; n++) {
                g[n] = fmaf(p, g[n], g_hloc[((cb0 + cc) * DS + n) * DI + d]);
                p *= e;
            }
        } else {
#pragma unroll
            for (int n = 0; n < DS; n++)
                g[n] = fmaf(__expf(A[n] * Sc), g[n],
                            g_hloc[((cb0 + cc) * DS + n) * DI + d]);
        }
    }

    size_t r0 = ((size_t)dir * BATCH + b) * LSEQ;
    int t0 = c * CL, t1 = min(LSEQ, t0 + CL);
    for (int t = t0; t < t1; t++) {
        size_t r = r0 + t;
        const float4* dbq  = (const float4*)(g_dbl  + r * XD);
        const float4* dbq2 = (const float4*)(g_dbl2 + r * XD);
        float4 qC0 = add4(__ldg(dbq + 7), __ldg(dbq2 + 7));
        float4 qC1 = add4(__ldg(dbq + 8), __ldg(dbq2 + 8));
        float4 qC2 = add4(__ldg(dbq + 9), __ldg(dbq2 + 9));
        float4 qC3 = add4(__ldg(dbq + 10), __ldg(dbq2 + 10));
        float dt = g_dt[r * DI + d];
        float Cv[DS] = {qC0.x, qC0.y, qC0.z, qC0.w, qC1.x, qC1.y, qC1.z, qC1.w,
                        qC2.x, qC2.y, qC2.z, qC2.w, qC3.x, qC3.y, qC3.z, qC3.w};
        float acc = 0.f;
        if (flag) {
            float e = __expf(dt * A0);
            float p = e;
#pragma unroll
            for (int n = 0; n < DS; n++) {
                g[n] *= p;
                acc = fmaf(g[n], Cv[n], acc);
                p *= e;
            }
        } else {
#pragma unroll
            for (int n = 0; n < DS; n++) {
                g[n] *= __expf(dt * A[n]);
                acc = fmaf(g[n], Cv[n], acc);
            }
        }
        g_y[r * DI + d] += acc;
    }
}

// ---------------- final: norm token 0 + head ---------------------------------
__global__ void k_final(const float* __restrict__ nfw, const float* __restrict__ hw,
                        const float* __restrict__ hb, float* __restrict__ out) {
    int b = blockIdx.x;
    int c = threadIdx.x;
    __shared__ float vn[DM];
    __shared__ float red[6];
    size_t o = ((size_t)b * LSEQ) * DM + c;
    float v = g_res[o] + g_hid[o] + g_hid2[o];
    float s = v * v;
#pragma unroll
    for (int ofs = 16; ofs > 0; ofs >>= 1) s += __shfl_xor_sync(0xffffffffu, s, ofs);
    if ((c & 31) == 0) red[c >> 5] = s;
    __syncthreads();
    float tot = red[0] + red[1] + red[2] + red[3] + red[4] + red[5];
    float rs = rsqrtf(tot / (float)DM + EPSV);
    vn[c] = v * rs * nfw[c];
    __syncthreads();
    if (c < NCLS) {
        float acc = hb[c];
        for (int j = 0; j < DM; j++) acc = fmaf(vn[j], hw[(size_t)c * DM + j], acc);
        out[b * NCLS + c] = acc;
    }
}

// ---------------- host --------------------------------------------------------
static float* symaddr(const void* sym) {
    void* p = nullptr;
    cudaGetSymbolAddress(&p, sym);
    return (float*)p;
}

extern "C" void kernel_launch(void* const* d_in, const int* in_sizes, int n_in,
                              void* d_out, int out_size) {
    (void)in_sizes; (void)n_in; (void)out_size;
    const float* x      = (const float*)d_in[0];
    const float* pe_w   = (const float*)d_in[1];
    const float* pe_b   = (const float*)d_in[2];
    const float* cls    = (const float*)d_in[3];
    const float* pos    = (const float*)d_in[4];
    const float* norm_w = (const float*)d_in[5];
    const float* ipw    = (const float*)d_in[6];
    const float* cw     = (const float*)d_in[7];
    const float* cb     = (const float*)d_in[8];
    const float* xpw    = (const float*)d_in[9];
    const float* dtw    = (const float*)d_in[10];
    const float* dtb    = (const float*)d_in[11];
    const float* Alog   = (const float*)d_in[12];
    const float* Ablog  = (const float*)d_in[13];
    const float* Dp     = (const float*)d_in[14];
    const float* opw    = (const float*)d_in[15];
    const float* nfw    = (const float*)d_in[16];
    const float* hw     = (const float*)d_in[17];
    const float* hb     = (const float*)d_in[18];
    float* out = (float*)d_out;

    float* p_hn   = symaddr(g_hn);
    float* p_xz   = symaddr(g_xz);
    float* p_xx   = symaddr(g_xx);
    float* p_dbl  = symaddr(g_dbl);
    float* p_dbl2 = symaddr(g_dbl2);

    k_prepA<<<(2 * DEPTH * DI + 127) / 128, 128>>>(Alog, Ablog);
    k_embed<<<dim3(LSEQ, BATCH), DM>>>(x, pe_w, pe_b, cls, pos);

    for (int l = 0; l < DEPTH; l++) {
        k_resnorm<<<ROWS, DM>>>(norm_w + (size_t)l * DM);

        // in_proj (3xtf32): M=1604, N=768, K=192  -> grid (12, 26, 1)
        k_mma<<<dim3(12, 26, 1), 256>>>(p_hn, ipw + (size_t)l * 2 * DI * DM,
                                        p_xz, p_xz, ROWS, 2 * DI, DM, DM, 2 * DI);

        k_conv<<<dim3((LSEQ + CONV_TT - 1) / CONV_TT, BATCH, 2), DI>>>(
            cw + (size_t)l * DI * 4, cb + (size_t)l * DI);

        // dbl (3xtf32, K-split x2): M=3208, N=44, K=2x192 -> grid (1, 51, 2)
        k_mma<<<dim3(1, 51, 2), 256>>>(p_xx, xpw + (size_t)l * XD * DI,
                                       p_dbl, p_dbl2, ROWS2, XD, DI, DI / 2, XD);

        k_scanA<<<dim3(NC, BATCH, 2), DI>>>(dtw + (size_t)l * DI * DR,
                                            dtb + (size_t)l * DI,
                                            Dp + (size_t)l * DI, l);
        k_scanC<<<dim3(NC - 1, BATCH, 2), DI>>>(l);

        // out_proj (3xtf32, gated A, K-split x2): grid (3, 26, 2)
        k_mma_out<<<dim3(3, 26, 2), 256>>>(opw + (size_t)l * DM * DI);
    }

    k_final<<<BATCH, DM>>>(nfw, hw, hb, out);
}

// round 16
// speedup vs baseline: 1.0468x; 1.0468x over previous
#include <cuda_runtime.h>
#include <math.h>

#define DEPTH 24
#define DM    192
#define DI    384
#define DS    16
#define DR    12
#define BATCH 4
#define LSEQ  401
#define NCLS  22
#define XD    44
#define EPSV  1e-5f
#define NC    31
#define CL    13
#define ROWS  (BATCH*LSEQ)     // 1604
#define ROWS2 (2*BATCH*LSEQ)   // 3208

// ---------------- scratch ----------------------------------------------------
__device__ float g_res [ROWS*DM];
__device__ float g_hid [ROWS*DM];
__device__ float g_hn  [ROWS*DM];
__device__ float g_xz  [ROWS*2*DI];
__device__ float g_xx  [ROWS2*DI];
__device__ float g_dt  [ROWS2*DI];
__device__ float g_dbl [ROWS2*XD];
__device__ float g_y   [ROWS2*DI];
__device__ float g_Aexp[2*DEPTH*DI*DS];
__device__ int   g_Aflag[2*DEPTH*DI];
__device__ float g_hloc[2*BATCH*NC*DS*DI];
__device__ float g_S   [2*BATCH*NC*DI];

__device__ __forceinline__ float siluf(float x) { return x / (1.f + __expf(-x)); }
__device__ __forceinline__ float softplusf(float x) {
    return x > 20.f ? x : log1pf(__expf(x));
}

// ---------------- prep: A = -exp(A_log); detect geometric structure ----------
__global__ void k_prepA(const float* __restrict__ Alog, const float* __restrict__ Ablog) {
    int i = blockIdx.x * blockDim.x + threadIdx.x;
    if (i >= 2 * DEPTH * DI) return;
    int dir = i / (DEPTH * DI);
    int rest = i - dir * (DEPTH * DI);
    const float* src = (dir ? Ablog : Alog) + (size_t)rest * DS;
    float A[DS];
#pragma unroll
    for (int n = 0; n < DS; n++) A[n] = -__expf(src[n]);
    float A0 = A[0];
    bool ok = true;
#pragma unroll
    for (int n = 1; n < DS; n++) {
        float tgt = (float)(n + 1) * A0;
        ok = ok && (fabsf(A[n] - tgt) <= 1e-4f * fabsf(tgt) + 1e-30f);
    }
#pragma unroll
    for (int n = 0; n < DS; n++) g_Aexp[(size_t)i * DS + n] = A[n];
    g_Aflag[i] = ok ? 1 : 0;
}

// ---------------- patch embed + cls + pos ------------------------------------
__global__ void k_embed(const float* __restrict__ x, const float* __restrict__ pew,
                        const float* __restrict__ peb, const float* __restrict__ cls,
                        const float* __restrict__ pos) {
    int t = blockIdx.x, b = blockIdx.y, c = threadIdx.x;
    float v;
    __shared__ float patch[256];
    if (t == 0) {
        v = cls[c] + pos[c];
    } else {
        int p = t - 1;
        int ph = p / 200, pw = p % 200;
        for (int i = c; i < 256; i += DM)
            patch[i] = x[(size_t)b * 32 * 3200 + (size_t)(ph * 16 + i / 16) * 3200
                         + pw * 16 + (i % 16)];
        __syncthreads();
        float acc = peb[c];
        const float* wc = pew + (size_t)c * 256;
#pragma unroll 8
        for (int i = 0; i < 256; i++) acc = fmaf(patch[i], __ldg(wc + i), acc);
        v = acc + pos[(size_t)t * DM + c];
    }
    size_t o = ((size_t)b * LSEQ + t) * DM + c;
    g_res[o] = v;
    g_hid[o] = v;
}

// ---------------- residual += hidden; rmsnorm --------------------------------
__global__ void k_resnorm(const float* __restrict__ nw) {
    int r = blockIdx.x;
    int c = threadIdx.x;
    __shared__ float red[6];
    size_t o = (size_t)r * DM + c;
    float v = g_res[o] + g_hid[o];
    g_res[o] = v;
    float s = v * v;
#pragma unroll
    for (int ofs = 16; ofs > 0; ofs >>= 1) s += __shfl_xor_sync(0xffffffffu, s, ofs);
    if ((c & 31) == 0) red[c >> 5] = s;
    __syncthreads();
    float tot = red[0] + red[1] + red[2] + red[3] + red[4] + red[5];
    float rs = rsqrtf(tot / (float)DM + EPSV);
    g_hn[o] = v * rs * nw[c];
}

// ---------------- generic SGEMM: C[M,N] = A[M,K] @ W[N,K]^T ------------------
template <int BM, int BN, int BK, int TM, int TN>
__global__ __launch_bounds__((BM / TM) * (BN / TN))
void sgemm_nt(const float* __restrict__ A, const float* __restrict__ W,
              float* __restrict__ C, int M, int N, int K) {
    constexpr int THR = (BM / TM) * (BN / TN);
    __shared__ float As[BK][BM + 4];
    __shared__ float Ws[BK][BN + 4];
    int tid = threadIdx.x;
    int tx = tid % (BN / TN);
    int ty = tid / (BN / TN);
    int row0 = blockIdx.y * BM;
    int col0 = blockIdx.x * BN;
    float acc[TM][TN];
#pragma unroll
    for (int i = 0; i < TM; i++)
#pragma unroll
        for (int j = 0; j < TN; j++) acc[i][j] = 0.f;

    for (int k0 = 0; k0 < K; k0 += BK) {
        for (int i = tid; i < BM * (BK / 4); i += THR) {
            int m = i / (BK / 4), kq = i % (BK / 4);
            float4 v = make_float4(0.f, 0.f, 0.f, 0.f);
            if (row0 + m < M)
                v = __ldg((const float4*)(A + (size_t)(row0 + m) * K + k0 + kq * 4));
            As[kq * 4 + 0][m] = v.x; As[kq * 4 + 1][m] = v.y;
            As[kq * 4 + 2][m] = v.z; As[kq * 4 + 3][m] = v.w;
        }
        for (int i = tid; i < BN * (BK / 4); i += THR) {
            int n = i / (BK / 4), kq = i % (BK / 4);
            float4 v = make_float4(0.f, 0.f, 0.f, 0.f);
            if (col0 + n < N)
                v = __ldg((const float4*)(W + (size_t)(col0 + n) * K + k0 + kq * 4));
            Ws[kq * 4 + 0][n] = v.x; Ws[kq * 4 + 1][n] = v.y;
            Ws[kq * 4 + 2][n] = v.z; Ws[kq * 4 + 3][n] = v.w;
        }
        __syncthreads();
#pragma unroll
        for (int k = 0; k < BK; k++) {
            float ra[TM], rb[TN];
#pragma unroll
            for (int i = 0; i < TM; i++) ra[i] = As[k][ty * TM + i];
#pragma unroll
            for (int j = 0; j < TN; j++) rb[j] = Ws[k][tx * TN + j];
#pragma unroll
            for (int i = 0; i < TM; i++)
#pragma unroll
                for (int j = 0; j < TN; j++) acc[i][j] = fmaf(ra[i], rb[j], acc[i][j]);
        }
        __syncthreads();
    }
#pragma unroll
    for (int i = 0; i < TM; i++) {
        int r = row0 + ty * TM + i;
        if (r >= M) continue;
#pragma unroll
        for (int j = 0; j < TN; j++) {
            int cc = col0 + tx * TN + j;
            if (cc < N) C[(size_t)r * N + cc] = acc[i][j];
        }
    }
}

// ---------------- out_proj GEMM with gated A: A = (yf+yb)*silu(z) ------------
#define OP_BM 32
#define OP_BN 64
#define OP_BK 16
__global__ __launch_bounds__(256)
void k_gemm_out(const float* __restrict__ W) {
    __shared__ float As[OP_BK][OP_BM + 4];
    __shared__ float Ws[OP_BK][OP_BN + 4];
    int tid = threadIdx.x;
    int tx = tid % 16;            // BN/TN = 64/4
    int ty = tid / 16;            // BM/TM = 32/2
    int row0 = blockIdx.y * OP_BM;
    int col0 = blockIdx.x * OP_BN;
    float acc[2][4] = {};

    for (int k0 = 0; k0 < DI; k0 += OP_BK) {
        if (tid < OP_BM * (OP_BK / 4)) {         // 128 loader tasks
            int m = tid >> 2, kq = tid & 3;
            int r = row0 + m;
            float4 a = make_float4(0.f, 0.f, 0.f, 0.f);
            if (r < ROWS) {
                int b = r / LSEQ, t = r % LSEQ;
                int d0 = k0 + kq * 4;
                float4 yf = __ldg((const float4*)(g_y + (size_t)r * DI + d0));
                size_t rb = ((size_t)(BATCH + b) * LSEQ + (LSEQ - 1 - t));
                float4 yb = __ldg((const float4*)(g_y + rb * DI + d0));
                float4 z4 = __ldg((const float4*)(g_xz + (size_t)r * 2 * DI + DI + d0));
                a.x = (yf.x + yb.x) * siluf(z4.x);
                a.y = (yf.y + yb.y) * siluf(z4.y);
                a.z = (yf.z + yb.z) * siluf(z4.z);
                a.w = (yf.w + yb.w) * siluf(z4.w);
            }
            As[kq * 4 + 0][m] = a.x; As[kq * 4 + 1][m] = a.y;
            As[kq * 4 + 2][m] = a.z; As[kq * 4 + 3][m] = a.w;
        }
        for (int i = tid; i < OP_BN * (OP_BK / 4); i += 256) {   // 256 tasks
            int n = i >> 2, kq = i & 3;
            float4 v = __ldg((const float4*)(W + (size_t)(col0 + n) * DI + k0 + kq * 4));
            Ws[kq * 4 + 0][n] = v.x; Ws[kq * 4 + 1][n] = v.y;
            Ws[kq * 4 + 2][n] = v.z; Ws[kq * 4 + 3][n] = v.w;
        }
        __syncthreads();
#pragma unroll
        for (int k = 0; k < OP_BK; k++) {
            float ra0 = As[k][ty * 2 + 0], ra1 = As[k][ty * 2 + 1];
            float rb[4];
#pragma unroll
            for (int j = 0; j < 4; j++) rb[j] = Ws[k][tx * 4 + j];
#pragma unroll
            for (int j = 0; j < 4; j++) {
                acc[0][j] = fmaf(ra0, rb[j], acc[0][j]);
                acc[1][j] = fmaf(ra1, rb[j], acc[1][j]);
            }
        }
        __syncthreads();
    }
#pragma unroll
    for (int i = 0; i < 2; i++) {
        int r = row0 + ty * 2 + i;
        if (r >= ROWS) continue;
#pragma unroll
        for (int j = 0; j < 4; j++)
            g_hid[(size_t)r * DM + col0 + tx * 4 + j] = acc[i][j];
    }
}

// ---------------- causal depthwise conv + silu (both directions) -------------
#define CONV_TT 16
__global__ void k_conv(const float* __restrict__ cw, const float* __restrict__ cb) {
    int dir = blockIdx.z, b = blockIdx.y, tile = blockIdx.x;
    int d = threadIdx.x;
    float w0 = cw[d * 4 + 0], w1 = cw[d * 4 + 1], w2 = cw[d * 4 + 2], w3 = cw[d * 4 + 3];
    float bi = cb[d];
    const float* xzb = g_xz + (size_t)b * LSEQ * 2 * DI + d;
    int t0 = tile * CONV_TT, t1 = min(LSEQ, t0 + CONV_TT);
    for (int t = t0; t < t1; t++) {
        float s = bi;
        if (dir == 0) {
            if (t >= 3) s = fmaf(w0, xzb[(size_t)(t - 3) * 2 * DI], s);
            if (t >= 2) s = fmaf(w1, xzb[(size_t)(t - 2) * 2 * DI], s);
            if (t >= 1) s = fmaf(w2, xzb[(size_t)(t - 1) * 2 * DI], s);
            s = fmaf(w3, xzb[(size_t)t * 2 * DI], s);
        } else {
            int base = LSEQ - 1 - t;
            s = fmaf(w3, xzb[(size_t)base * 2 * DI], s);
            if (t >= 1) s = fmaf(w2, xzb[(size_t)(base + 1) * 2 * DI], s);
            if (t >= 2) s = fmaf(w1, xzb[(size_t)(base + 2) * 2 * DI], s);
            if (t >= 3) s = fmaf(w0, xzb[(size_t)(base + 3) * 2 * DI], s);
        }
        g_xx[(((size_t)dir * BATCH + b) * LSEQ + t) * DI + d] = siluf(s);
    }
}

// ---------------- scan pass A: chunk-local scan (dt_proj fused, stores dt) ---
__global__ __launch_bounds__(DI)
void k_scanA(const float* __restrict__ dtw, const float* __restrict__ dtb,
             const float* __restrict__ Dpl, int l) {
    int dir = blockIdx.z, b = blockIdx.y, c = blockIdx.x;
    int d = threadIdx.x;
    const float* Ap = g_Aexp + (((size_t)dir * DEPTH + l) * DI + d) * DS;
    float A[DS];
#pragma unroll
    for (int n = 0; n < DS; n++) A[n] = Ap[n];
    int flag = g_Aflag[((size_t)dir * DEPTH + l) * DI + d];
    float A0 = A[0];
    float wdt[DR];
#pragma unroll
    for (int j = 0; j < DR; j++) wdt[j] = __ldg(dtw + (size_t)d * DR + j);
    float db0 = dtb[d], Dd = Dpl[d];

    size_t r0 = ((size_t)dir * BATCH + b) * LSEQ;
    int t0 = c * CL, t1 = min(LSEQ, t0 + CL);
    float h[DS];
#pragma unroll
    for (int n = 0; n < DS; n++) h[n] = 0.f;
    float S = 0.f;

    for (int t = t0; t < t1; t++) {
        size_t r = r0 + t;
        const float4* dbq = (const float4*)(g_dbl + r * XD);
        float4 q0 = __ldg(dbq + 0), q1 = __ldg(dbq + 1), q2 = __ldg(dbq + 2);
        float4 qB0 = __ldg(dbq + 3), qB1 = __ldg(dbq + 4),
               qB2 = __ldg(dbq + 5), qB3 = __ldg(dbq + 6);
        float4 qC0 = __ldg(dbq + 7), qC1 = __ldg(dbq + 8),
               qC2 = __ldg(dbq + 9), qC3 = __ldg(dbq + 10);
        float d1 = db0, d2 = 0.f;
        d1 = fmaf(q0.x, wdt[0], d1); d2 = fmaf(q0.y, wdt[1], d2);
        d1 = fmaf(q0.z, wdt[2], d1); d2 = fmaf(q0.w, wdt[3], d2);
        d1 = fmaf(q1.x, wdt[4], d1); d2 = fmaf(q1.y, wdt[5], d2);
        d1 = fmaf(q1.z, wdt[6], d1); d2 = fmaf(q1.w, wdt[7], d2);
        d1 = fmaf(q2.x, wdt[8], d1); d2 = fmaf(q2.y, wdt[9], d2);
        d1 = fmaf(q2.z, wdt[10], d1); d2 = fmaf(q2.w, wdt[11], d2);
        float dt = softplusf(d1 + d2);
        g_dt[r * DI + d] = dt;
        float xv = g_xx[r * DI + d];
        float dtx = dt * xv;
        S += dt;
        float Bv[DS] = {qB0.x, qB0.y, qB0.z, qB0.w, qB1.x, qB1.y, qB1.z, qB1.w,
                        qB2.x, qB2.y, qB2.z, qB2.w, qB3.x, qB3.y, qB3.z, qB3.w};
        float Cv[DS] = {qC0.x, qC0.y, qC0.z, qC0.w, qC1.x, qC1.y, qC1.z, qC1.w,
                        qC2.x, qC2.y, qC2.z, qC2.w, qC3.x, qC3.y, qC3.z, qC3.w};
        float acc = 0.f;
        if (flag) {
            float e = __expf(dt * A0);
            float p = e;
#pragma unroll
            for (int n = 0; n < DS; n++) {
                h[n] = fmaf(p, h[n], dtx * Bv[n]);
                acc = fmaf(h[n], Cv[n], acc);
                p *= e;
            }
        } else {
#pragma unroll
            for (int n = 0; n < DS; n++) {
                float a = __expf(dt * A[n]);
                h[n] = fmaf(a, h[n], dtx * Bv[n]);
                acc = fmaf(h[n], Cv[n], acc);
            }
        }
        g_y[r * DI + d] = acc + xv * Dd;
    }
    size_t cb_ = ((size_t)dir * BATCH + b) * NC + c;
#pragma unroll
    for (int n = 0; n < DS; n++) g_hloc[(cb_ * DS + n) * DI + d] = h[n];
    g_S[cb_ * DI + d] = S;
}

// ---------------- scan pass C: carry reconstruction + fixup (loads dt) -------
__global__ __launch_bounds__(DI)
void k_scanC(int l) {
    int dir = blockIdx.z, b = blockIdx.y, c = blockIdx.x + 1;
    int d = threadIdx.x;
    const float* Ap = g_Aexp + (((size_t)dir * DEPTH + l) * DI + d) * DS;
    float A[DS];
#pragma unroll
    for (int n = 0; n < DS; n++) A[n] = Ap[n];
    int flag = g_Aflag[((size_t)dir * DEPTH + l) * DI + d];
    float A0 = A[0];

    size_t cb0 = ((size_t)dir * BATCH + b) * NC;
    float g[DS];
#pragma unroll
    for (int n = 0; n < DS; n++) g[n] = 0.f;
    for (int cc = 0; cc < c; cc++) {
        float Sc = g_S[(cb0 + cc) * DI + d];
        if (flag) {
            float e = __expf(A0 * Sc);
            float p = e;
#pragma unroll
            for (int n = 0; n < DS; n++) {
                g[n] = fmaf(p, g[n], g_hloc[((cb0 + cc) * DS + n) * DI + d]);
                p *= e;
            }
        } else {
#pragma unroll
            for (int n = 0; n < DS; n++)
                g[n] = fmaf(__expf(A[n] * Sc), g[n],
                            g_hloc[((cb0 + cc) * DS + n) * DI + d]);
        }
    }

    size_t r0 = ((size_t)dir * BATCH + b) * LSEQ;
    int t0 = c * CL, t1 = min(LSEQ, t0 + CL);
    for (int t = t0; t < t1; t++) {
        size_t r = r0 + t;
        const float4* dbq = (const float4*)(g_dbl + r * XD);
        float4 qC0 = __ldg(dbq + 7), qC1 = __ldg(dbq + 8),
               qC2 = __ldg(dbq + 9), qC3 = __ldg(dbq + 10);
        float dt = g_dt[r * DI + d];
        float Cv[DS] = {qC0.x, qC0.y, qC0.z, qC0.w, qC1.x, qC1.y, qC1.z, qC1.w,
                        qC2.x, qC2.y, qC2.z, qC2.w, qC3.x, qC3.y, qC3.z, qC3.w};
        float acc = 0.f;
        if (flag) {
            float e = __expf(dt * A0);
            float p = e;
#pragma unroll
            for (int n = 0; n < DS; n++) {
                g[n] *= p;
                acc = fmaf(g[n], Cv[n], acc);
                p *= e;
            }
        } else {
#pragma unroll
            for (int n = 0; n < DS; n++) {
                g[n] *= __expf(dt * A[n]);
                acc = fmaf(g[n], Cv[n], acc);
            }
        }
        g_y[r * DI + d] += acc;
    }
}

// ---------------- final: norm token 0 + head ---------------------------------
__global__ void k_final(const float* __restrict__ nfw, const float* __restrict__ hw,
                        const float* __restrict__ hb, float* __restrict__ out) {
    int b = blockIdx.x;
    int c = threadIdx.x;
    __shared__ float vn[DM];
    __shared__ float red[6];
    size_t o = ((size_t)b * LSEQ) * DM + c;
    float v = g_res[o] + g_hid[o];
    float s = v * v;
#pragma unroll
    for (int ofs = 16; ofs > 0; ofs >>= 1) s += __shfl_xor_sync(0xffffffffu, s, ofs);
    if ((c & 31) == 0) red[c >> 5] = s;
    __syncthreads();
    float tot = red[0] + red[1] + red[2] + red[3] + red[4] + red[5];
    float rs = rsqrtf(tot / (float)DM + EPSV);
    vn[c] = v * rs * nfw[c];
    __syncthreads();
    if (c < NCLS) {
        float acc = hb[c];
        for (int j = 0; j < DM; j++) acc = fmaf(vn[j], hw[(size_t)c * DM + j], acc);
        out[b * NCLS + c] = acc;
    }
}

// ---------------- host --------------------------------------------------------
static float* symaddr(const void* sym) {
    void* p = nullptr;
    cudaGetSymbolAddress(&p, sym);
    return (float*)p;
}

extern "C" void kernel_launch(void* const* d_in, const int* in_sizes, int n_in,
                              void* d_out, int out_size) {
    (void)in_sizes; (void)n_in; (void)out_size;
    const float* x      = (const float*)d_in[0];
    const float* pe_w   = (const float*)d_in[1];
    const float* pe_b   = (const float*)d_in[2];
    const float* cls    = (const float*)d_in[3];
    const float* pos    = (const float*)d_in[4];
    const float* norm_w = (const float*)d_in[5];
    const float* ipw    = (const float*)d_in[6];
    const float* cw     = (const float*)d_in[7];
    const float* cb     = (const float*)d_in[8];
    const float* xpw    = (const float*)d_in[9];
    const float* dtw    = (const float*)d_in[10];
    const float* dtb    = (const float*)d_in[11];
    const float* Alog   = (const float*)d_in[12];
    const float* Ablog  = (const float*)d_in[13];
    const float* Dp     = (const float*)d_in[14];
    const float* opw    = (const float*)d_in[15];
    const float* nfw    = (const float*)d_in[16];
    const float* hw     = (const float*)d_in[17];
    const float* hb     = (const float*)d_in[18];
    float* out = (float*)d_out;

    float* p_hn  = symaddr(g_hn);
    float* p_xz  = symaddr(g_xz);
    float* p_xx  = symaddr(g_xx);
    float* p_dbl = symaddr(g_dbl);

    k_prepA<<<(2 * DEPTH * DI + 127) / 128, 128>>>(Alog, Ablog);
    k_embed<<<dim3(LSEQ, BATCH), DM>>>(x, pe_w, pe_b, cls, pos);

    for (int l = 0; l < DEPTH; l++) {
        k_resnorm<<<ROWS, DM>>>(norm_w + (size_t)l * DM);

        // xz = hn @ ipw^T : M=1604, N=768, K=192  (R3 shape, 312 blocks)
        sgemm_nt<64, 64, 16, 4, 4><<<dim3((2 * DI) / 64, (ROWS + 63) / 64), 256>>>(
            p_hn, ipw + (size_t)l * 2 * DI * DM, p_xz, ROWS, 2 * DI, DM);

        k_conv<<<dim3((LSEQ + CONV_TT - 1) / CONV_TT, BATCH, 2), DI>>>(
            cw + (size_t)l * DI * 4, cb + (size_t)l * DI);

        // dbl = xx @ xpw^T : M=3208, N=44, K=384  (201 blocks x 384 thr)
        sgemm_nt<16, 48, 16, 1, 2><<<dim3(1, (ROWS2 + 15) / 16), 384>>>(
            p_xx, xpw + (size_t)l * XD * DI, p_dbl, ROWS2, XD, DI);

        k_scanA<<<dim3(NC, BATCH, 2), DI>>>(dtw + (size_t)l * DI * DR,
                                            dtb + (size_t)l * DI,
                                            Dp + (size_t)l * DI, l);
        k_scanC<<<dim3(NC - 1, BATCH, 2), DI>>>(l);

        // hid = gated @ opw^T (R3 shape, 153 blocks)
        k_gemm_out<<<dim3(DM / OP_BN, (ROWS + OP_BM - 1) / OP_BM), 256>>>(
            opw + (size_t)l * DM * DI);
    }

    k_final<<<BATCH, DM>>>(nfw, hw, hb, out);
}

// round 17
// speedup vs baseline: 1.1091x; 1.0595x over previous
#include <cuda_runtime.h>
#include <math.h>

#define DEPTH 24
#define DM    192
#define DI    384
#define DS    16
#define DR    12
#define BATCH 4
#define LSEQ  401
#define NCLS  22
#define XD    44
#define EPSV  1e-5f
#define NC    31
#define CL    13
#define ROWS  (BATCH*LSEQ)     // 1604
#define ROWS2 (2*BATCH*LSEQ)   // 3208

// ---------------- scratch ----------------------------------------------------
__device__ float g_res [ROWS*DM];
__device__ float g_hid [ROWS*DM];
__device__ float g_hn  [ROWS*DM];
__device__ float g_xz  [ROWS*2*DI];
__device__ float g_xx  [ROWS2*DI];
__device__ float g_dbl [ROWS2*XD];
__device__ float g_y   [ROWS2*DI];
__device__ float g_Aexp[2*DEPTH*DI*DS];
__device__ int   g_Aflag[2*DEPTH*DI];
__device__ float g_hloc[2*BATCH*NC*DS*DI];
__device__ float g_cin [2*BATCH*NC*DS*DI];
__device__ float g_S   [2*BATCH*NC*DI];

__device__ __forceinline__ float siluf(float x) { return x / (1.f + __expf(-x)); }
__device__ __forceinline__ float softplusf(float x) {
    return x > 20.f ? x : log1pf(__expf(x));
}

// ---------------- prep: A = -exp(A_log); detect geometric structure ----------
__global__ void k_prepA(const float* __restrict__ Alog, const float* __restrict__ Ablog) {
    int i = blockIdx.x * blockDim.x + threadIdx.x;
    if (i >= 2 * DEPTH * DI) return;
    int dir = i / (DEPTH * DI);
    int rest = i - dir * (DEPTH * DI);
    const float* src = (dir ? Ablog : Alog) + (size_t)rest * DS;
    float A[DS];
#pragma unroll
    for (int n = 0; n < DS; n++) A[n] = -__expf(src[n]);
    float A0 = A[0];
    bool ok = true;
#pragma unroll
    for (int n = 1; n < DS; n++) {
        float tgt = (float)(n + 1) * A0;
        ok = ok && (fabsf(A[n] - tgt) <= 1e-4f * fabsf(tgt) + 1e-30f);
    }
#pragma unroll
    for (int n = 0; n < DS; n++) g_Aexp[(size_t)i * DS + n] = A[n];
    g_Aflag[i] = ok ? 1 : 0;
}

// ---------------- patch embed + cls + pos ------------------------------------
__global__ void k_embed(const float* __restrict__ x, const float* __restrict__ pew,
                        const float* __restrict__ peb, const float* __restrict__ cls,
                        const float* __restrict__ pos) {
    int t = blockIdx.x, b = blockIdx.y, c = threadIdx.x;
    float v;
    __shared__ float patch[256];
    if (t == 0) {
        v = cls[c] + pos[c];
    } else {
        int p = t - 1;
        int ph = p / 200, pw = p % 200;
        for (int i = c; i < 256; i += DM)
            patch[i] = x[(size_t)b * 32 * 3200 + (size_t)(ph * 16 + i / 16) * 3200
                         + pw * 16 + (i % 16)];
        __syncthreads();
        float acc = peb[c];
        const float* wc = pew + (size_t)c * 256;
#pragma unroll 8
        for (int i = 0; i < 256; i++) acc = fmaf(patch[i], __ldg(wc + i), acc);
        v = acc + pos[(size_t)t * DM + c];
    }
    size_t o = ((size_t)b * LSEQ + t) * DM + c;
    g_res[o] = v;
    g_hid[o] = v;
}

// ---------------- residual += hidden; rmsnorm --------------------------------
__global__ void k_resnorm(const float* __restrict__ nw) {
    int r = blockIdx.x;
    int c = threadIdx.x;
    __shared__ float red[6];
    size_t o = (size_t)r * DM + c;
    float v = g_res[o] + g_hid[o];
    g_res[o] = v;
    float s = v * v;
#pragma unroll
    for (int ofs = 16; ofs > 0; ofs >>= 1) s += __shfl_xor_sync(0xffffffffu, s, ofs);
    if ((c & 31) == 0) red[c >> 5] = s;
    __syncthreads();
    float tot = red[0] + red[1] + red[2] + red[3] + red[4] + red[5];
    float rs = rsqrtf(tot / (float)DM + EPSV);
    g_hn[o] = v * rs * nw[c];
}

// ---------------- generic SGEMM: C[M,N] = A[M,K] @ W[N,K]^T ------------------
template <int BM, int BN, int BK, int TM, int TN>
__global__ __launch_bounds__((BM / TM) * (BN / TN))
void sgemm_nt(const float* __restrict__ A, const float* __restrict__ W,
              float* __restrict__ C, int M, int N, int K) {
    constexpr int THR = (BM / TM) * (BN / TN);
    __shared__ float As[BK][BM + 4];
    __shared__ float Ws[BK][BN + 4];
    int tid = threadIdx.x;
    int tx = tid % (BN / TN);
    int ty = tid / (BN / TN);
    int row0 = blockIdx.y * BM;
    int col0 = blockIdx.x * BN;
    float acc[TM][TN];
#pragma unroll
    for (int i = 0; i < TM; i++)
#pragma unroll
        for (int j = 0; j < TN; j++) acc[i][j] = 0.f;

    for (int k0 = 0; k0 < K; k0 += BK) {
        for (int i = tid; i < BM * (BK / 4); i += THR) {
            int m = i / (BK / 4), kq = i % (BK / 4);
            float4 v = make_float4(0.f, 0.f, 0.f, 0.f);
            if (row0 + m < M)
                v = __ldg((const float4*)(A + (size_t)(row0 + m) * K + k0 + kq * 4));
            As[kq * 4 + 0][m] = v.x; As[kq * 4 + 1][m] = v.y;
            As[kq * 4 + 2][m] = v.z; As[kq * 4 + 3][m] = v.w;
        }
        for (int i = tid; i < BN * (BK / 4); i += THR) {
            int n = i / (BK / 4), kq = i % (BK / 4);
            float4 v = make_float4(0.f, 0.f, 0.f, 0.f);
            if (col0 + n < N)
                v = __ldg((const float4*)(W + (size_t)(col0 + n) * K + k0 + kq * 4));
            Ws[kq * 4 + 0][n] = v.x; Ws[kq * 4 + 1][n] = v.y;
            Ws[kq * 4 + 2][n] = v.z; Ws[kq * 4 + 3][n] = v.w;
        }
        __syncthreads();
#pragma unroll
        for (int k = 0; k < BK; k++) {
            float ra[TM], rb[TN];
#pragma unroll
            for (int i = 0; i < TM; i++) ra[i] = As[k][ty * TM + i];
#pragma unroll
            for (int j = 0; j < TN; j++) rb[j] = Ws[k][tx * TN + j];
#pragma unroll
            for (int i = 0; i < TM; i++)
#pragma unroll
                for (int j = 0; j < TN; j++) acc[i][j] = fmaf(ra[i], rb[j], acc[i][j]);
        }
        __syncthreads();
    }
#pragma unroll
    for (int i = 0; i < TM; i++) {
        int r = row0 + ty * TM + i;
        if (r >= M) continue;
#pragma unroll
        for (int j = 0; j < TN; j++) {
            int cc = col0 + tx * TN + j;
            if (cc < N) C[(size_t)r * N + cc] = acc[i][j];
        }
    }
}

// ---------------- out_proj GEMM with gated A: A = (yf+yb)*silu(z) ------------
#define OP_BM 32
#define OP_BN 64
#define OP_BK 16
__global__ __launch_bounds__(256)
void k_gemm_out(const float* __restrict__ W) {
    __shared__ float As[OP_BK][OP_BM + 4];
    __shared__ float Ws[OP_BK][OP_BN + 4];
    int tid = threadIdx.x;
    int tx = tid % 16;            // BN/TN = 64/4
    int ty = tid / 16;            // BM/TM = 32/2
    int row0 = blockIdx.y * OP_BM;
    int col0 = blockIdx.x * OP_BN;
    float acc[2][4] = {};

    for (int k0 = 0; k0 < DI; k0 += OP_BK) {
        if (tid < OP_BM * (OP_BK / 4)) {         // 128 loader tasks
            int m = tid >> 2, kq = tid & 3;
            int r = row0 + m;
            float4 a = make_float4(0.f, 0.f, 0.f, 0.f);
            if (r < ROWS) {
                int b = r / LSEQ, t = r % LSEQ;
                int d0 = k0 + kq * 4;
                float4 yf = __ldg((const float4*)(g_y + (size_t)r * DI + d0));
                size_t rb = ((size_t)(BATCH + b) * LSEQ + (LSEQ - 1 - t));
                float4 yb = __ldg((const float4*)(g_y + rb * DI + d0));
                float4 z4 = __ldg((const float4*)(g_xz + (size_t)r * 2 * DI + DI + d0));
                a.x = (yf.x + yb.x) * siluf(z4.x);
                a.y = (yf.y + yb.y) * siluf(z4.y);
                a.z = (yf.z + yb.z) * siluf(z4.z);
                a.w = (yf.w + yb.w) * siluf(z4.w);
            }
            As[kq * 4 + 0][m] = a.x; As[kq * 4 + 1][m] = a.y;
            As[kq * 4 + 2][m] = a.z; As[kq * 4 + 3][m] = a.w;
        }
        for (int i = tid; i < OP_BN * (OP_BK / 4); i += 256) {   // 256 tasks
            int n = i >> 2, kq = i & 3;
            float4 v = __ldg((const float4*)(W + (size_t)(col0 + n) * DI + k0 + kq * 4));
            Ws[kq * 4 + 0][n] = v.x; Ws[kq * 4 + 1][n] = v.y;
            Ws[kq * 4 + 2][n] = v.z; Ws[kq * 4 + 3][n] = v.w;
        }
        __syncthreads();
#pragma unroll
        for (int k = 0; k < OP_BK; k++) {
            float ra0 = As[k][ty * 2 + 0], ra1 = As[k][ty * 2 + 1];
            float rb[4];
#pragma unroll
            for (int j = 0; j < 4; j++) rb[j] = Ws[k][tx * 4 + j];
#pragma unroll
            for (int j = 0; j < 4; j++) {
                acc[0][j] = fmaf(ra0, rb[j], acc[0][j]);
                acc[1][j] = fmaf(ra1, rb[j], acc[1][j]);
            }
        }
        __syncthreads();
    }
#pragma unroll
    for (int i = 0; i < 2; i++) {
        int r = row0 + ty * 2 + i;
        if (r >= ROWS) continue;
#pragma unroll
        for (int j = 0; j < 4; j++)
            g_hid[(size_t)r * DM + col0 + tx * 4 + j] = acc[i][j];
    }
}

// ---------------- causal depthwise conv + silu (both directions) -------------
#define CONV_TT 16
__global__ void k_conv(const float* __restrict__ cw, const float* __restrict__ cb) {
    int dir = blockIdx.z, b = blockIdx.y, tile = blockIdx.x;
    int d = threadIdx.x;
    float w0 = cw[d * 4 + 0], w1 = cw[d * 4 + 1], w2 = cw[d * 4 + 2], w3 = cw[d * 4 + 3];
    float bi = cb[d];
    const float* xzb = g_xz + (size_t)b * LSEQ * 2 * DI + d;
    int t0 = tile * CONV_TT, t1 = min(LSEQ, t0 + CONV_TT);
    for (int t = t0; t < t1; t++) {
        float s = bi;
        if (dir == 0) {
            if (t >= 3) s = fmaf(w0, xzb[(size_t)(t - 3) * 2 * DI], s);
            if (t >= 2) s = fmaf(w1, xzb[(size_t)(t - 2) * 2 * DI], s);
            if (t >= 1) s = fmaf(w2, xzb[(size_t)(t - 1) * 2 * DI], s);
            s = fmaf(w3, xzb[(size_t)t * 2 * DI], s);
        } else {
            int base = LSEQ - 1 - t;
            s = fmaf(w3, xzb[(size_t)base * 2 * DI], s);
            if (t >= 1) s = fmaf(w2, xzb[(size_t)(base + 1) * 2 * DI], s);
            if (t >= 2) s = fmaf(w1, xzb[(size_t)(base + 2) * 2 * DI], s);
            if (t >= 3) s = fmaf(w0, xzb[(size_t)(base + 3) * 2 * DI], s);
        }
        g_xx[(((size_t)dir * BATCH + b) * LSEQ + t) * DI + d] = siluf(s);
    }
}

// ---------------- scan pass A: chunk-local scan (dt_proj fused) --------------
__global__ __launch_bounds__(DI)
void k_scanA(const float* __restrict__ dtw, const float* __restrict__ dtb,
             const float* __restrict__ Dpl, int l) {
    int dir = blockIdx.z, b = blockIdx.y, c = blockIdx.x;
    int d = threadIdx.x;
    const float* Ap = g_Aexp + (((size_t)dir * DEPTH + l) * DI + d) * DS;
    float A[DS];
#pragma unroll
    for (int n = 0; n < DS; n++) A[n] = Ap[n];
    int flag = g_Aflag[((size_t)dir * DEPTH + l) * DI + d];
    float A0 = A[0];
    float wdt[DR];
#pragma unroll
    for (int j = 0; j < DR; j++) wdt[j] = __ldg(dtw + (size_t)d * DR + j);
    float db0 = dtb[d], Dd = Dpl[d];

    size_t r0 = ((size_t)dir * BATCH + b) * LSEQ;
    int t0 = c * CL, t1 = min(LSEQ, t0 + CL);
    float h[DS];
#pragma unroll
    for (int n = 0; n < DS; n++) h[n] = 0.f;
    float S = 0.f;

    for (int t = t0; t < t1; t++) {
        size_t r = r0 + t;
        const float4* dbq = (const float4*)(g_dbl + r * XD);
        float4 q0 = __ldg(dbq + 0), q1 = __ldg(dbq + 1), q2 = __ldg(dbq + 2);
        float4 qB0 = __ldg(dbq + 3), qB1 = __ldg(dbq + 4),
               qB2 = __ldg(dbq + 5), qB3 = __ldg(dbq + 6);
        float4 qC0 = __ldg(dbq + 7), qC1 = __ldg(dbq + 8),
               qC2 = __ldg(dbq + 9), qC3 = __ldg(dbq + 10);
        float d1 = db0, d2 = 0.f;
        d1 = fmaf(q0.x, wdt[0], d1); d2 = fmaf(q0.y, wdt[1], d2);
        d1 = fmaf(q0.z, wdt[2], d1); d2 = fmaf(q0.w, wdt[3], d2);
        d1 = fmaf(q1.x, wdt[4], d1); d2 = fmaf(q1.y, wdt[5], d2);
        d1 = fmaf(q1.z, wdt[6], d1); d2 = fmaf(q1.w, wdt[7], d2);
        d1 = fmaf(q2.x, wdt[8], d1); d2 = fmaf(q2.y, wdt[9], d2);
        d1 = fmaf(q2.z, wdt[10], d1); d2 = fmaf(q2.w, wdt[11], d2);
        float dt = softplusf(d1 + d2);
        float xv = g_xx[r * DI + d];
        float dtx = dt * xv;
        S += dt;
        float Bv[DS] = {qB0.x, qB0.y, qB0.z, qB0.w, qB1.x, qB1.y, qB1.z, qB1.w,
                        qB2.x, qB2.y, qB2.z, qB2.w, qB3.x, qB3.y, qB3.z, qB3.w};
        float Cv[DS] = {qC0.x, qC0.y, qC0.z, qC0.w, qC1.x, qC1.y, qC1.z, qC1.w,
                        qC2.x, qC2.y, qC2.z, qC2.w, qC3.x, qC3.y, qC3.z, qC3.w};
        float acc = 0.f;
        if (flag) {
            float e = __expf(dt * A0);
            float p = e;
#pragma unroll
            for (int n = 0; n < DS; n++) {
                h[n] = fmaf(p, h[n], dtx * Bv[n]);
                acc = fmaf(h[n], Cv[n], acc);
                p *= e;
            }
        } else {
#pragma unroll
            for (int n = 0; n < DS; n++) {
                float a = __expf(dt * A[n]);
                h[n] = fmaf(a, h[n], dtx * Bv[n]);
                acc = fmaf(h[n], Cv[n], acc);
            }
        }
        g_y[r * DI + d] = acc + xv * Dd;
    }
    size_t cb_ = ((size_t)dir * BATCH + b) * NC + c;
#pragma unroll
    for (int n = 0; n < DS; n++) g_hloc[(cb_ * DS + n) * DI + d] = h[n];
    g_S[cb_ * DI + d] = S;
}

// ---------- prefix combine: carry-in per chunk, one thread per (d, n) --------
// 49152 independent scans of length NC-1. grid (24, BATCH, 2), 256 threads.
__global__ __launch_bounds__(256)
void k_prefix(int l) {
    int dir = blockIdx.z, b = blockIdx.y;
    int pair = blockIdx.x * 256 + threadIdx.x;   // 0 .. DI*DS-1
    int n = pair / DI;
    int d = pair - n * DI;
    size_t cb0 = ((size_t)dir * BATCH + b) * NC;
    float An = g_Aexp[((((size_t)dir * DEPTH + l) * DI + d)) * DS + n];
    float g = 0.f;
    // prefetch chunk 0
    float Sc = g_S[cb0 * DI + d];
    float hl = g_hloc[(cb0 * DS + n) * DI + d];
    for (int cc = 0; cc < NC - 1; cc++) {
        float Sn = 0.f, hn2 = 0.f;
        if (cc + 1 < NC - 1) {
            Sn  = g_S[(cb0 + cc + 1) * DI + d];
            hn2 = g_hloc[((cb0 + cc + 1) * DS + n) * DI + d];
        }
        g = fmaf(__expf(An * Sc), g, hl);
        g_cin[((cb0 + cc + 1) * DS + n) * DI + d] = g;
        Sc = Sn; hl = hn2;
    }
}

// ---------------- scan pass C: carry load + fixup ----------------------------
__global__ __launch_bounds__(DI)
void k_scanC(const float* __restrict__ dtw, const float* __restrict__ dtb, int l) {
    int dir = blockIdx.z, b = blockIdx.y, c = blockIdx.x + 1;
    int d = threadIdx.x;
    const float* Ap = g_Aexp + (((size_t)dir * DEPTH + l) * DI + d) * DS;
    float A[DS];
#pragma unroll
    for (int n = 0; n < DS; n++) A[n] = Ap[n];
    int flag = g_Aflag[((size_t)dir * DEPTH + l) * DI + d];
    float A0 = A[0];
    float wdt[DR];
#pragma unroll
    for (int j = 0; j < DR; j++) wdt[j] = __ldg(dtw + (size_t)d * DR + j);
    float db0 = dtb[d];

    size_t cb0 = ((size_t)dir * BATCH + b) * NC;
    float g[DS];
#pragma unroll
    for (int n = 0; n < DS; n++)
        g[n] = g_cin[((cb0 + c) * DS + n) * DI + d];

    size_t r0 = ((size_t)dir * BATCH + b) * LSEQ;
    int t0 = c * CL, t1 = min(LSEQ, t0 + CL);
    for (int t = t0; t < t1; t++) {
        size_t r = r0 + t;
        const float4* dbq = (const float4*)(g_dbl + r * XD);
        float4 q0 = __ldg(dbq + 0), q1 = __ldg(dbq + 1), q2 = __ldg(dbq + 2);
        float4 qC0 = __ldg(dbq + 7), qC1 = __ldg(dbq + 8),
               qC2 = __ldg(dbq + 9), qC3 = __ldg(dbq + 10);
        float d1 = db0, d2 = 0.f;
        d1 = fmaf(q0.x, wdt[0], d1); d2 = fmaf(q0.y, wdt[1], d2);
        d1 = fmaf(q0.z, wdt[2], d1); d2 = fmaf(q0.w, wdt[3], d2);
        d1 = fmaf(q1.x, wdt[4], d1); d2 = fmaf(q1.y, wdt[5], d2);
        d1 = fmaf(q1.z, wdt[6], d1); d2 = fmaf(q1.w, wdt[7], d2);
        d1 = fmaf(q2.x, wdt[8], d1); d2 = fmaf(q2.y, wdt[9], d2);
        d1 = fmaf(q2.z, wdt[10], d1); d2 = fmaf(q2.w, wdt[11], d2);
        float dt = softplusf(d1 + d2);
        float Cv[DS] = {qC0.x, qC0.y, qC0.z, qC0.w, qC1.x, qC1.y, qC1.z, qC1.w,
                        qC2.x, qC2.y, qC2.z, qC2.w, qC3.x, qC3.y, qC3.z, qC3.w};
        float acc = 0.f;
        if (flag) {
            float e = __expf(dt * A0);
            float p = e;
#pragma unroll
            for (int n = 0; n < DS; n++) {
                g[n] *= p;
                acc = fmaf(g[n], Cv[n], acc);
                p *= e;
            }
        } else {
#pragma unroll
            for (int n = 0; n < DS; n++) {
                g[n] *= __expf(dt * A[n]);
                acc = fmaf(g[n], Cv[n], acc);
            }
        }
        g_y[r * DI + d] += acc;
    }
}

// ---------------- final: norm token 0 + head ---------------------------------
__global__ void k_final(const float* __restrict__ nfw, const float* __restrict__ hw,
                        const float* __restrict__ hb, float* __restrict__ out) {
    int b = blockIdx.x;
    int c = threadIdx.x;
    __shared__ float vn[DM];
    __shared__ float red[6];
    size_t o = ((size_t)b * LSEQ) * DM + c;
    float v = g_res[o] + g_hid[o];
    float s = v * v;
#pragma unroll
    for (int ofs = 16; ofs > 0; ofs >>= 1) s += __shfl_xor_sync(0xffffffffu, s, ofs);
    if ((c & 31) == 0) red[c >> 5] = s;
    __syncthreads();
    float tot = red[0] + red[1] + red[2] + red[3] + red[4] + red[5];
    float rs = rsqrtf(tot / (float)DM + EPSV);
    vn[c] = v * rs * nfw[c];
    __syncthreads();
    if (c < NCLS) {
        float acc = hb[c];
        for (int j = 0; j < DM; j++) acc = fmaf(vn[j], hw[(size_t)c * DM + j], acc);
        out[b * NCLS + c] = acc;
    }
}

// ---------------- host --------------------------------------------------------
static float* symaddr(const void* sym) {
    void* p = nullptr;
    cudaGetSymbolAddress(&p, sym);
    return (float*)p;
}

extern "C" void kernel_launch(void* const* d_in, const int* in_sizes, int n_in,
                              void* d_out, int out_size) {
    (void)in_sizes; (void)n_in; (void)out_size;
    const float* x      = (const float*)d_in[0];
    const float* pe_w   = (const float*)d_in[1];
    const float* pe_b   = (const float*)d_in[2];
    const float* cls    = (const float*)d_in[3];
    const float* pos    = (const float*)d_in[4];
    const float* norm_w = (const float*)d_in[5];
    const float* ipw    = (const float*)d_in[6];
    const float* cw     = (const float*)d_in[7];
    const float* cb     = (const float*)d_in[8];
    const float* xpw    = (const float*)d_in[9];
    const float* dtw    = (const float*)d_in[10];
    const float* dtb    = (const float*)d_in[11];
    const float* Alog   = (const float*)d_in[12];
    const float* Ablog  = (const float*)d_in[13];
    const float* Dp     = (const float*)d_in[14];
    const float* opw    = (const float*)d_in[15];
    const float* nfw    = (const float*)d_in[16];
    const float* hw     = (const float*)d_in[17];
    const float* hb     = (const float*)d_in[18];
    float* out = (float*)d_out;

    float* p_hn  = symaddr(g_hn);
    float* p_xz  = symaddr(g_xz);
    float* p_xx  = symaddr(g_xx);
    float* p_dbl = symaddr(g_dbl);

    k_prepA<<<(2 * DEPTH * DI + 127) / 128, 128>>>(Alog, Ablog);
    k_embed<<<dim3(LSEQ, BATCH), DM>>>(x, pe_w, pe_b, cls, pos);

    for (int l = 0; l < DEPTH; l++) {
        k_resnorm<<<ROWS, DM>>>(norm_w + (size_t)l * DM);

        // xz = hn @ ipw^T : M=1604, N=768, K=192  (R3 shape, 312 blocks)
        sgemm_nt<64, 64, 16, 4, 4><<<dim3((2 * DI) / 64, (ROWS + 63) / 64), 256>>>(
            p_hn, ipw + (size_t)l * 2 * DI * DM, p_xz, ROWS, 2 * DI, DM);

        k_conv<<<dim3((LSEQ + CONV_TT - 1) / CONV_TT, BATCH, 2), DI>>>(
            cw + (size_t)l * DI * 4, cb + (size_t)l * DI);

        // dbl = xx @ xpw^T : M=3208, N=44, K=384  (R3 shape, 101 blocks)
        sgemm_nt<32, 64, 16, 2, 4><<<dim3(1, (ROWS2 + 31) / 32), 256>>>(
            p_xx, xpw + (size_t)l * XD * DI, p_dbl, ROWS2, XD, DI);

        k_scanA<<<dim3(NC, BATCH, 2), DI>>>(dtw + (size_t)l * DI * DR,
                                            dtb + (size_t)l * DI,
                                            Dp + (size_t)l * DI, l);

        // O(NC) carry prefix: 192 blocks x 256 thr, one thread per (d, n)
        k_prefix<<<dim3((DI * DS) / 256, BATCH, 2), 256>>>(l);

        k_scanC<<<dim3(NC - 1, BATCH, 2), DI>>>(dtw + (size_t)l * DI * DR,
                                                dtb + (size_t)l * DI, l);

        // hid = gated @ opw^T (R3 shape, 153 blocks)
        k_gemm_out<<<dim3(DM / OP_BN, (ROWS + OP_BM - 1) / OP_BM), 256>>>(
            opw + (size_t)l * DM * DI);
    }

    k_final<<<BATCH, DM>>>(nfw, hw, hb, out);
}